// round 12
// baseline (speedup 1.0000x reference)
#include <cuda_runtime.h>
#include <cuda_fp16.h>
#include <cstdint>
#include <math.h>

// Problem constants
#define NB   8
#define FF   16
#define SS   196
#define DD   1024
#define HH   8
#define HD   128
#define LL   (1 + FF * SS)      // 3137
#define MM   (NB * LL)          // 25096
#define NH   (NB * HH)          // 64

// ---------------------------------------------------------------------------
// Scratch (__device__ globals — allocation-free rule)
// ---------------------------------------------------------------------------
__device__ __half g_xh [(size_t)MM * DD];     // fp16 GEMM input; reused for LN2 out
__device__ __half g_lnh[(size_t)MM * DD];     // fp16 LN1 out
__device__ float g_tmp0[(size_t)MM * DD];
__device__ float g_q   [(size_t)MM * DD];
__device__ float g_k   [(size_t)MM * DD];
__device__ float g_v   [(size_t)MM * DD];
__device__ float g_attn[(size_t)MM * DD];
__device__ __half g_win [(size_t)DD * DD];    // Wt_in  [n][k]
__device__ __half g_wout[(size_t)DD * DD];    // Wt_out [n][k]
__device__ __half g_wqkv[(size_t)3 * DD * DD];// Wt_q|Wt_k|Wt_v stacked on n

// ---------------------------------------------------------------------------
// PTX helpers (baseline sm_80 features — no tcgen05 on this target)
// ---------------------------------------------------------------------------
__device__ __forceinline__ uint32_t smem_u32(const void* p) {
    uint32_t a;
    asm("{ .reg .u64 t; cvta.to.shared.u64 t, %1; cvt.u32.u64 %0, t; }" : "=r"(a) : "l"(p));
    return a;
}
#define CP_ASYNC16(dst, src) \
    asm volatile("cp.async.cg.shared.global [%0], [%1], 16;" :: "r"(dst), "l"(src))
#define CP_COMMIT() asm volatile("cp.async.commit_group;" ::: "memory")
#define CP_WAIT(n)  asm volatile("cp.async.wait_group %0;" :: "n"(n) : "memory")

__device__ __forceinline__ void ldsm_x4(uint32_t* r, uint32_t addr) {
    asm volatile("ldmatrix.sync.aligned.m8n8.x4.shared.b16 {%0,%1,%2,%3}, [%4];"
                 : "=r"(r[0]), "=r"(r[1]), "=r"(r[2]), "=r"(r[3]) : "r"(addr));
}
__device__ __forceinline__ void mma16816(float* c, const uint32_t* a, const uint32_t* b) {
    asm volatile(
        "mma.sync.aligned.m16n8k16.row.col.f32.f16.f16.f32 "
        "{%0,%1,%2,%3}, {%4,%5,%6,%7}, {%8,%9}, {%0,%1,%2,%3};"
        : "+f"(c[0]), "+f"(c[1]), "+f"(c[2]), "+f"(c[3])
        : "r"(a[0]), "r"(a[1]), "r"(a[2]), "r"(a[3]), "r"(b[0]), "r"(b[1]));
}

// ---------------------------------------------------------------------------
// fp16 mma.sync GEMM (unchanged from R11 — two consecutive wins):
//   CTA 128x128x64, 8 warps (2x4), warp tile 64x32, 3-stage cp.async, 2 CTAs/SM.
// MODE 0: fp32 row-major out + bias (NN=1024, C0).
// MODE 1: fused-QKV head-split scatter (NN=3072, C0/C1/C2 = q/k/v).
// ---------------------------------------------------------------------------
#define BM      128
#define BN      128
#define BK      64
#define NSTAGE  3
#define APAD    72                         // halves; 144-byte row stride
#define STAGE_H ((BM + BN) * APAD)         // 18432 halves per stage
#define ATILE_H (BM * APAD)                // 9216 halves
#define GEMM_SMEM (NSTAGE * STAGE_H * 2)   // 110592 bytes
#define KCH     16                         // 1024 / 64

template<int MODE>
__global__ void __launch_bounds__(256, 2)
gemm_mma(const __half* __restrict__ A, const __half* __restrict__ B,
         const float* __restrict__ bias,
         float* __restrict__ C0, float* __restrict__ C1, float* __restrict__ C2)
{
    extern __shared__ __half sm[];
    const uint32_t smem_base = smem_u32(sm);
    const int tid  = threadIdx.x;
    const int wid  = tid >> 5;
    const int lane = tid & 31;
    const int warp_m = wid >> 2;
    const int warp_n = wid & 3;
    const int bm = blockIdx.y * BM;
    const int bn = blockIdx.x * BN;

    const int lrow = tid >> 3;
    const int lkq  = (tid & 7) * 8;

    float c[4][4][4];
#pragma unroll
    for (int i = 0; i < 4; i++)
#pragma unroll
        for (int j = 0; j < 4; j++)
#pragma unroll
            for (int r = 0; r < 4; r++) c[i][j][r] = 0.f;

#pragma unroll
    for (int s = 0; s < NSTAGE - 1; s++) {
        const int kk = s * BK;
        const uint32_t abase = smem_base + s * STAGE_H * 2;
        const uint32_t bbase = abase + ATILE_H * 2;
#pragma unroll
        for (int i = 0; i < 4; i++) {
            int row = lrow + i * 32;
            int gr  = bm + row; if (gr >= MM) gr = MM - 1;
            CP_ASYNC16(abase + (row * APAD + lkq) * 2, A + (size_t)gr * DD + kk + lkq);
            CP_ASYNC16(bbase + (row * APAD + lkq) * 2, B + (size_t)(bn + row) * DD + kk + lkq);
        }
        CP_COMMIT();
    }

    for (int kc = 0; kc < KCH; kc++) {
        CP_WAIT(NSTAGE - 2);
        __syncthreads();

        {
            const int ld = kc + NSTAGE - 1;
            if (ld < KCH) {
                const int s = ld % NSTAGE;
                const int kk = ld * BK;
                const uint32_t abase = smem_base + s * STAGE_H * 2;
                const uint32_t bbase = abase + ATILE_H * 2;
#pragma unroll
                for (int i = 0; i < 4; i++) {
                    int row = lrow + i * 32;
                    int gr  = bm + row; if (gr >= MM) gr = MM - 1;
                    CP_ASYNC16(abase + (row * APAD + lkq) * 2, A + (size_t)gr * DD + kk + lkq);
                    CP_ASYNC16(bbase + (row * APAD + lkq) * 2, B + (size_t)(bn + row) * DD + kk + lkq);
                }
            }
            CP_COMMIT();
        }

        const int s = kc % NSTAGE;
        const uint32_t abase = smem_base + s * STAGE_H * 2;
        const uint32_t bbase = abase + ATILE_H * 2;
        const uint32_t arow = abase + ((warp_m * 64 + (lane & 15)) * APAD + (lane >> 4) * 8) * 2;
        const uint32_t brow = bbase + ((warp_n * 32 + (lane & 15)) * APAD + (lane >> 4) * 8) * 2;
#pragma unroll
        for (int ks = 0; ks < 4; ks++) {
            uint32_t af[4][4];
            uint32_t bq[2][4];
#pragma unroll
            for (int mt = 0; mt < 4; mt++)
                ldsm_x4(af[mt], arow + (mt * 16 * APAD + ks * 16) * 2);
#pragma unroll
            for (int np = 0; np < 2; np++)
                ldsm_x4(bq[np], brow + (np * 16 * APAD + ks * 16) * 2);
#pragma unroll
            for (int mt = 0; mt < 4; mt++)
#pragma unroll
                for (int np = 0; np < 2; np++) {
                    uint32_t b0[2] = { bq[np][0], bq[np][2] };
                    uint32_t b1[2] = { bq[np][1], bq[np][3] };
                    mma16816(c[mt][np * 2 + 0], af[mt], b0);
                    mma16816(c[mt][np * 2 + 1], af[mt], b1);
                }
        }
    }

    const int rfrag = lane >> 2;
    const int cfrag = (lane & 3) * 2;
#pragma unroll
    for (int mt = 0; mt < 4; mt++) {
        const int rm0 = bm + warp_m * 64 + mt * 16 + rfrag;
#pragma unroll
        for (int half = 0; half < 2; half++) {
            const int rm = rm0 + half * 8;
            if (rm >= MM) continue;
            int b_ = 0, l_ = 0;
            if (MODE == 1) { b_ = rm / LL; l_ = rm - b_ * LL; }
#pragma unroll
            for (int nt = 0; nt < 4; nt++) {
                const int cn = bn + warp_n * 32 + nt * 8 + cfrag;
                float2 vv = make_float2(c[mt][nt][half * 2 + 0], c[mt][nt][half * 2 + 1]);
                if (MODE == 0) {
                    vv.x += bias[cn];
                    vv.y += bias[cn + 1];
                    *reinterpret_cast<float2*>(&C0[(size_t)rm * DD + cn]) = vv;
                } else {
                    const int mat = cn >> 10;
                    const int cc  = cn & 1023;
                    const int h   = cc >> 7;
                    const int d   = cc & 127;
                    float* base = (mat == 0) ? C0 : (mat == 1) ? C1 : C2;
                    *reinterpret_cast<float2*>(
                        &base[(((size_t)(b_ * HH + h)) * LL + l_) * HD + d]) = vv;
                }
            }
        }
    }
}

// ---------------------------------------------------------------------------
// fp32 -> fp16 conversion
// ---------------------------------------------------------------------------
__global__ void __launch_bounds__(256)
conv_half(const float* __restrict__ in, __half* __restrict__ out)
{
    const size_t row = blockIdx.x;
    const int tid = threadIdx.x;
#pragma unroll
    for (int i = 0; i < 4; i++) {
        int cidx = i * 256 + tid;
        out[row * DD + cidx] = __float2half(in[row * DD + cidx]);
    }
}

// Weight transpose (batched): W[k][n] fp32 -> Wt[n][k] fp16
__global__ void __launch_bounds__(256)
conv_w3(const float* __restrict__ Wa, const float* __restrict__ Wb,
        const float* __restrict__ Wc,
        __half* __restrict__ Ta, __half* __restrict__ Tb, __half* __restrict__ Tc)
{
    const float* W = (blockIdx.z == 0) ? Wa : (blockIdx.z == 1) ? Wb : Wc;
    __half*      T = (blockIdx.z == 0) ? Ta : (blockIdx.z == 1) ? Tb : Tc;
    __shared__ float tile[32][33];
    const int n0 = blockIdx.x * 32, k0 = blockIdx.y * 32;
    const int tx = threadIdx.x & 31, ty = threadIdx.x >> 5;
#pragma unroll
    for (int i = ty; i < 32; i += 8)
        tile[i][tx] = W[(size_t)(k0 + i) * DD + n0 + tx];
    __syncthreads();
#pragma unroll
    for (int i = ty; i < 32; i += 8)
        T[(size_t)(n0 + i) * DD + k0 + tx] = __float2half(tile[tx][i]);
}

__global__ void __launch_bounds__(256)
conv_w2(const float* __restrict__ Wa, const float* __restrict__ Wb,
        __half* __restrict__ Ta, __half* __restrict__ Tb)
{
    const float* W = (blockIdx.z == 0) ? Wa : Wb;
    __half*      T = (blockIdx.z == 0) ? Ta : Tb;
    __shared__ float tile[32][33];
    const int n0 = blockIdx.x * 32, k0 = blockIdx.y * 32;
    const int tx = threadIdx.x & 31, ty = threadIdx.x >> 5;
#pragma unroll
    for (int i = ty; i < 32; i += 8)
        tile[i][tx] = W[(size_t)(k0 + i) * DD + n0 + tx];
    __syncthreads();
#pragma unroll
    for (int i = ty; i < 32; i += 8)
        T[(size_t)(n0 + i) * DD + k0 + tx] = __float2half(tile[tx][i]);
}

// ---------------------------------------------------------------------------
// LayerNorm over D=1024, fp16 output.
// ---------------------------------------------------------------------------
template<int GATHER>
__global__ void __launch_bounds__(256)
ln_half(const float* __restrict__ in, const float* __restrict__ g,
        const float* __restrict__ beta, __half* __restrict__ out)
{
    const int row = blockIdx.x;
    const int tid = threadIdx.x;
    int b_ = 0, l_ = 0;
    if (GATHER) { b_ = row / LL; l_ = row - b_ * LL; }

    float v[4];
    float s = 0.f, ss = 0.f;
#pragma unroll
    for (int i = 0; i < 4; i++) {
        int cidx = i * 256 + tid;
        float x;
        if (GATHER) {
            int h = cidx >> 7, d = cidx & 127;
            x = in[(((size_t)(b_ * HH + h)) * LL + l_) * HD + d];
        } else {
            x = in[(size_t)row * DD + cidx];
        }
        v[i] = x; s += x; ss += x * x;
    }

    __shared__ float rs[32], rss[32];
#pragma unroll
    for (int o = 16; o > 0; o >>= 1) {
        s  += __shfl_xor_sync(0xffffffffu, s,  o);
        ss += __shfl_xor_sync(0xffffffffu, ss, o);
    }
    int warp = tid >> 5, lane = tid & 31;
    if (lane == 0) { rs[warp] = s; rss[warp] = ss; }
    __syncthreads();
    if (warp == 0) {
        float s2  = (lane < 8) ? rs[lane]  : 0.f;
        float ss2 = (lane < 8) ? rss[lane] : 0.f;
#pragma unroll
        for (int o = 4; o > 0; o >>= 1) {
            s2  += __shfl_xor_sync(0xffffffffu, s2,  o);
            ss2 += __shfl_xor_sync(0xffffffffu, ss2, o);
        }
        if (lane == 0) { rs[0] = s2; rss[0] = ss2; }
    }
    __syncthreads();
    s = rs[0]; ss = rss[0];

    float mean = s * (1.f / 1024.f);
    float var  = ss * (1.f / 1024.f) - mean * mean;
    float rstd = rsqrtf(var + 1e-5f);

#pragma unroll
    for (int i = 0; i < 4; i++) {
        int cidx = i * 256 + tid;
        out[(size_t)row * DD + cidx] =
            __float2half((v[i] - mean) * rstd * g[cidx] + beta[cidx]);
    }
}

// ---------------------------------------------------------------------------
// Temporal attention — register-blocked, low smem-traffic version.
// One block per (bh, s): 16 q-frames x 17 keys x HD=128.
// Scores: 136 threads (17 j x 8 d-slices), 16 f-accumulators in regs,
//         ks padded to 129 so the j-spread is bank-conflict-free.
// Output: thread = (d, f-group); vs loaded once per (j,d), sc broadcast.
// Deterministic tree reductions only (no atomics).
// ---------------------------------------------------------------------------
__global__ void __launch_bounds__(256)
attn_temporal(const float* __restrict__ q, const float* __restrict__ k,
              const float* __restrict__ v, float* __restrict__ out,
              const int* __restrict__ att_type)
{
    if (*att_type != 1) return;
    const int blk = blockIdx.x;
    const int bh  = blk / SS;
    const int s   = blk - bh * SS;
    const int featIdx = blk % NH;        // jnp.tile head-scramble (verified R1)

    __shared__ float qs[FF][HD + 1];
    __shared__ float ks[FF + 1][HD + 1];
    __shared__ float vs[FF + 1][HD];
    __shared__ float spart[8][FF][FF + 1];
    __shared__ float sc[FF][FF + 1];

    const int tid = threadIdx.x;
    const float* qb = q + (size_t)bh * LL * HD;
    const float* kb = k + (size_t)bh * LL * HD;
    const float* vb = v + (size_t)bh * LL * HD;
    const float* kf = k + (size_t)featIdx * LL * HD;
    const float* vf = v + (size_t)featIdx * LL * HD;

    // --- load tiles ------------------------------------------------------
    for (int i = tid; i < FF * HD; i += 256) {
        int f = i >> 7, d = i & 127;
        qs[f][d] = qb[(size_t)(1 + f * SS + s) * HD + d];
    }
    for (int i = tid; i < (FF + 1) * HD; i += 256) {
        int j = i >> 7, d = i & 127;
        if (j == 0) { ks[0][d] = kf[d]; vs[0][d] = vf[d]; }
        else {
            size_t l = (size_t)(1 + (j - 1) * SS + s) * HD + d;
            ks[j][d] = kb[l];
            vs[j][d] = vb[l];
        }
    }
    __syncthreads();

    // --- scores: register-blocked over f ---------------------------------
    if (tid < 136) {
        const int j     = tid % 17;
        const int slice = tid / 17;          // 0..7, 16 d each
        float acc[FF];
#pragma unroll
        for (int f = 0; f < FF; f++) acc[f] = 0.f;
#pragma unroll
        for (int dd = 0; dd < 16; dd++) {
            const int d = slice * 16 + dd;
            const float kv = ks[j][d];
#pragma unroll
            for (int f = 0; f < FF; f++) acc[f] += qs[f][d] * kv;
        }
#pragma unroll
        for (int f = 0; f < FF; f++) spart[slice][f][j] = acc[f];
    }
    __syncthreads();

    // deterministic slice reduction -> sc
    for (int p = tid; p < FF * (FF + 1); p += 256) {
        const int f = p / (FF + 1);
        const int j = p - f * (FF + 1);
        float a = 0.f;
#pragma unroll
        for (int sl = 0; sl < 8; sl++) a += spart[sl][f][j];
        sc[f][j] = a * 0.08838834764831844f;   // 1/sqrt(128)
    }
    __syncthreads();

    // --- softmax per query row (17 keys) ---------------------------------
    if (tid < FF) {
        float mx = sc[tid][0];
#pragma unroll
        for (int j = 1; j <= FF; j++) mx = fmaxf(mx, sc[tid][j]);
        float sum = 0.f;
#pragma unroll
        for (int j = 0; j <= FF; j++) {
            float e = expf(sc[tid][j] - mx);
            sc[tid][j] = e; sum += e;
        }
        float inv = 1.f / sum;
#pragma unroll
        for (int j = 0; j <= FF; j++) sc[tid][j] *= inv;
    }
    __syncthreads();

    // --- output: vs loaded once per (j,d); sc warp-broadcast -------------
    {
        const int d = tid & 127;
        const int g = tid >> 7;              // f-group: 0 -> f 0..7, 1 -> f 8..15
        float acc8[8];
#pragma unroll
        for (int f8 = 0; f8 < 8; f8++) acc8[f8] = 0.f;
#pragma unroll
        for (int j = 0; j <= FF; j++) {
            const float vv = vs[j][d];
#pragma unroll
            for (int f8 = 0; f8 < 8; f8++)
                acc8[f8] += sc[g * 8 + f8][j] * vv;
        }
#pragma unroll
        for (int f8 = 0; f8 < 8; f8++) {
            const int f = g * 8 + f8;
            out[(size_t)bh * LL * HD + (size_t)(1 + f * SS + s) * HD + d] = acc8[f8];
        }
    }

    // feature token passes q through (once per bh)
    if (s == 0) {
        for (int d = tid; d < HD; d += 256)
            out[(size_t)bh * LL * HD + d] = qb[d];
    }
}

// ---------------------------------------------------------------------------
// Spatial attention fallback (att_type != 1; unused with this dataset)
// ---------------------------------------------------------------------------
__global__ void __launch_bounds__(256)
attn_spatial(const float* __restrict__ q, const float* __restrict__ k,
             const float* __restrict__ v, float* __restrict__ out,
             const int* __restrict__ att_type)
{
    if (*att_type == 1) return;
    const int bh = blockIdx.x / FF;
    const int f  = blockIdx.x - bh * FF;
    const int featIdx = blockIdx.x % NH;

    const float* qb = q + (size_t)bh * LL * HD;
    const float* kb = k + (size_t)bh * LL * HD;
    const float* vb = v + (size_t)bh * LL * HD;
    const float* kf = k + (size_t)featIdx * LL * HD;
    const float* vf = v + (size_t)featIdx * LL * HD;

    __shared__ float qs[HD];
    __shared__ float sc[SS + 1];
    __shared__ float red0;

    const int tid = threadIdx.x;
    for (int s = 0; s < SS; s++) {
        int lq = 1 + f * SS + s;
        for (int d = tid; d < HD; d += 256) qs[d] = qb[(size_t)lq * HD + d];
        __syncthreads();

        for (int j = tid; j <= SS; j += 256) {
            const float* kr = (j == 0) ? kf : &kb[(size_t)(1 + f * SS + (j - 1)) * HD];
            float a = 0.f;
            for (int d = 0; d < HD; d++) a += qs[d] * kr[d];
            sc[j] = a * 0.08838834764831844f;
        }
        __syncthreads();

        if (tid == 0) {
            float mx = sc[0];
            for (int j = 1; j <= SS; j++) mx = fmaxf(mx, sc[j]);
            float sum = 0.f;
            for (int j = 0; j <= SS; j++) { float e = expf(sc[j] - mx); sc[j] = e; sum += e; }
            red0 = 1.f / sum;
        }
        __syncthreads();
        float inv = red0;

        for (int d = tid; d < HD; d += 256) {
            float a = 0.f;
            for (int j = 0; j <= SS; j++) {
                const float* vr = (j == 0) ? vf : &vb[(size_t)(1 + f * SS + (j - 1)) * HD];
                a += sc[j] * vr[d];
            }
            out[(size_t)bh * LL * HD + (size_t)lq * HD + d] = a * inv;
        }
        __syncthreads();
    }
    if (f == 0) {
        for (int d = tid; d < HD; d += 256)
            out[(size_t)bh * LL * HD + d] = qb[d];
    }
}

// ---------------------------------------------------------------------------
// Launch
// ---------------------------------------------------------------------------
extern "C" void kernel_launch(void* const* d_in, const int* in_sizes, int n_in,
                              void* d_out, int out_size)
{
    const float* x       = (const float*)d_in[0];
    const float* W_in    = (const float*)d_in[1];
    const float* b_in    = (const float*)d_in[2];
    const float* g_in    = (const float*)d_in[3];
    const float* beta_in = (const float*)d_in[4];
    const float* W_q     = (const float*)d_in[5];
    const float* W_k     = (const float*)d_in[6];
    const float* W_v     = (const float*)d_in[7];
    const float* g_out_p = (const float*)d_in[8];
    const float* beta_out= (const float*)d_in[9];
    const float* W_out   = (const float*)d_in[10];
    const float* b_out   = (const float*)d_in[11];
    const int*   att_type= (const int*)d_in[12];
    float* out = (float*)d_out;

    __half *p_xh, *p_lnh, *p_win, *p_wout, *p_wqkv;
    float *p_tmp0, *p_q, *p_k, *p_v, *p_attn;
    cudaGetSymbolAddress((void**)&p_xh,   g_xh);
    cudaGetSymbolAddress((void**)&p_lnh,  g_lnh);
    cudaGetSymbolAddress((void**)&p_tmp0, g_tmp0);
    cudaGetSymbolAddress((void**)&p_q,    g_q);
    cudaGetSymbolAddress((void**)&p_k,    g_k);
    cudaGetSymbolAddress((void**)&p_v,    g_v);
    cudaGetSymbolAddress((void**)&p_attn, g_attn);
    cudaGetSymbolAddress((void**)&p_win,  g_win);
    cudaGetSymbolAddress((void**)&p_wout, g_wout);
    cudaGetSymbolAddress((void**)&p_wqkv, g_wqkv);

    cudaFuncSetAttribute(gemm_mma<0>, cudaFuncAttributeMaxDynamicSharedMemorySize, GEMM_SMEM);
    cudaFuncSetAttribute(gemm_mma<1>, cudaFuncAttributeMaxDynamicSharedMemorySize, GEMM_SMEM);

    dim3 wg3(32, 32, 3), wg2(32, 32, 2);
    conv_w3<<<wg3, 256>>>(W_in, W_q, W_k, p_win, p_wqkv, p_wqkv + (size_t)DD * DD);
    conv_w2<<<wg2, 256>>>(W_v, W_out, p_wqkv + (size_t)2 * DD * DD, p_wout);
    conv_half<<<MM, 256>>>(x, p_xh);

    dim3 g1(DD / BN, (MM + BM - 1) / BM);          // (8, 197)
    dim3 g3(3 * DD / BN, (MM + BM - 1) / BM);      // (24, 197)

    gemm_mma<0><<<g1, 256, GEMM_SMEM>>>(p_xh, p_win, b_in, p_tmp0, nullptr, nullptr);
    ln_half<0><<<MM, 256>>>(p_tmp0, g_in, beta_in, p_lnh);
    gemm_mma<1><<<g3, 256, GEMM_SMEM>>>(p_lnh, p_wqkv, nullptr, p_q, p_k, p_v);

    attn_temporal<<<NH * SS, 256>>>(p_q, p_k, p_v, p_attn, att_type);
    attn_spatial <<<NH * FF, 256>>>(p_q, p_k, p_v, p_attn, att_type);

    ln_half<1><<<MM, 256>>>(p_attn, g_out_p, beta_out, p_xh);
    gemm_mma<0><<<g1, 256, GEMM_SMEM>>>(p_xh, p_wout, b_out, out, nullptr, nullptr);
}

// round 15
// speedup vs baseline: 1.5312x; 1.5312x over previous
#include <cuda_runtime.h>
#include <cuda_fp16.h>
#include <cstdint>
#include <math.h>

// Problem constants
#define NB   8
#define FF   16
#define SS   196
#define DD   1024
#define HH   8
#define HD   128
#define LL   (1 + FF * SS)      // 3137
#define MM   (NB * LL)          // 25096
#define NH   (NB * HH)          // 64

// ---------------------------------------------------------------------------
// Scratch (__device__ globals — allocation-free rule)
// ---------------------------------------------------------------------------
__device__ __half g_xh [(size_t)MM * DD];     // fp16 GEMM input; reused for LN2 out
__device__ __half g_lnh[(size_t)MM * DD];     // fp16 LN1 out
__device__ float g_tmp0[(size_t)MM * DD];
__device__ float g_q   [(size_t)MM * DD];
__device__ float g_k   [(size_t)MM * DD];
__device__ float g_v   [(size_t)MM * DD];
__device__ float g_attn[(size_t)MM * DD];
__device__ __half g_win [(size_t)DD * DD];    // Wt_in  [n][k]
__device__ __half g_wout[(size_t)DD * DD];    // Wt_out [n][k]
__device__ __half g_wqkv[(size_t)3 * DD * DD];// Wt_q|Wt_k|Wt_v stacked on n

// ---------------------------------------------------------------------------
// PTX helpers (baseline sm_80 features — no tcgen05 on this target)
// ---------------------------------------------------------------------------
__device__ __forceinline__ uint32_t smem_u32(const void* p) {
    uint32_t a;
    asm("{ .reg .u64 t; cvta.to.shared.u64 t, %1; cvt.u32.u64 %0, t; }" : "=r"(a) : "l"(p));
    return a;
}
#define CP_ASYNC16(dst, src) \
    asm volatile("cp.async.cg.shared.global [%0], [%1], 16;" :: "r"(dst), "l"(src))
#define CP_COMMIT() asm volatile("cp.async.commit_group;" ::: "memory")
#define CP_WAIT(n)  asm volatile("cp.async.wait_group %0;" :: "n"(n) : "memory")

__device__ __forceinline__ void ldsm_x4(uint32_t* r, uint32_t addr) {
    asm volatile("ldmatrix.sync.aligned.m8n8.x4.shared.b16 {%0,%1,%2,%3}, [%4];"
                 : "=r"(r[0]), "=r"(r[1]), "=r"(r[2]), "=r"(r[3]) : "r"(addr));
}
__device__ __forceinline__ void mma16816(float* c, const uint32_t* a, const uint32_t* b) {
    asm volatile(
        "mma.sync.aligned.m16n8k16.row.col.f32.f16.f16.f32 "
        "{%0,%1,%2,%3}, {%4,%5,%6,%7}, {%8,%9}, {%0,%1,%2,%3};"
        : "+f"(c[0]), "+f"(c[1]), "+f"(c[2]), "+f"(c[3])
        : "r"(a[0]), "r"(a[1]), "r"(a[2]), "r"(a[3]), "r"(b[0]), "r"(b[1]));
}

// ---------------------------------------------------------------------------
// fp16 mma.sync GEMM (unchanged — wins R10/R11):
//   CTA 128x128x64, 8 warps (2x4), warp tile 64x32, 3-stage cp.async, 2 CTAs/SM.
// MODE 0: fp32 row-major out + bias (NN=1024, C0).
// MODE 1: fused-QKV head-split scatter (NN=3072, C0/C1/C2 = q/k/v).
// ---------------------------------------------------------------------------
#define BM      128
#define BN      128
#define BK      64
#define NSTAGE  3
#define APAD    72                         // halves; 144-byte row stride
#define STAGE_H ((BM + BN) * APAD)         // 18432 halves per stage
#define ATILE_H (BM * APAD)                // 9216 halves
#define GEMM_SMEM (NSTAGE * STAGE_H * 2)   // 110592 bytes
#define KCH     16                         // 1024 / 64

template<int MODE>
__global__ void __launch_bounds__(256, 2)
gemm_mma(const __half* __restrict__ A, const __half* __restrict__ B,
         const float* __restrict__ bias,
         float* __restrict__ C0, float* __restrict__ C1, float* __restrict__ C2)
{
    extern __shared__ __half sm[];
    const uint32_t smem_base = smem_u32(sm);
    const int tid  = threadIdx.x;
    const int wid  = tid >> 5;
    const int lane = tid & 31;
    const int warp_m = wid >> 2;
    const int warp_n = wid & 3;
    const int bm = blockIdx.y * BM;
    const int bn = blockIdx.x * BN;

    const int lrow = tid >> 3;
    const int lkq  = (tid & 7) * 8;

    float c[4][4][4];
#pragma unroll
    for (int i = 0; i < 4; i++)
#pragma unroll
        for (int j = 0; j < 4; j++)
#pragma unroll
            for (int r = 0; r < 4; r++) c[i][j][r] = 0.f;

#pragma unroll
    for (int s = 0; s < NSTAGE - 1; s++) {
        const int kk = s * BK;
        const uint32_t abase = smem_base + s * STAGE_H * 2;
        const uint32_t bbase = abase + ATILE_H * 2;
#pragma unroll
        for (int i = 0; i < 4; i++) {
            int row = lrow + i * 32;
            int gr  = bm + row; if (gr >= MM) gr = MM - 1;
            CP_ASYNC16(abase + (row * APAD + lkq) * 2, A + (size_t)gr * DD + kk + lkq);
            CP_ASYNC16(bbase + (row * APAD + lkq) * 2, B + (size_t)(bn + row) * DD + kk + lkq);
        }
        CP_COMMIT();
    }

    for (int kc = 0; kc < KCH; kc++) {
        CP_WAIT(NSTAGE - 2);
        __syncthreads();

        {
            const int ld = kc + NSTAGE - 1;
            if (ld < KCH) {
                const int s = ld % NSTAGE;
                const int kk = ld * BK;
                const uint32_t abase = smem_base + s * STAGE_H * 2;
                const uint32_t bbase = abase + ATILE_H * 2;
#pragma unroll
                for (int i = 0; i < 4; i++) {
                    int row = lrow + i * 32;
                    int gr  = bm + row; if (gr >= MM) gr = MM - 1;
                    CP_ASYNC16(abase + (row * APAD + lkq) * 2, A + (size_t)gr * DD + kk + lkq);
                    CP_ASYNC16(bbase + (row * APAD + lkq) * 2, B + (size_t)(bn + row) * DD + kk + lkq);
                }
            }
            CP_COMMIT();
        }

        const int s = kc % NSTAGE;
        const uint32_t abase = smem_base + s * STAGE_H * 2;
        const uint32_t bbase = abase + ATILE_H * 2;
        const uint32_t arow = abase + ((warp_m * 64 + (lane & 15)) * APAD + (lane >> 4) * 8) * 2;
        const uint32_t brow = bbase + ((warp_n * 32 + (lane & 15)) * APAD + (lane >> 4) * 8) * 2;
#pragma unroll
        for (int ks = 0; ks < 4; ks++) {
            uint32_t af[4][4];
            uint32_t bq[2][4];
#pragma unroll
            for (int mt = 0; mt < 4; mt++)
                ldsm_x4(af[mt], arow + (mt * 16 * APAD + ks * 16) * 2);
#pragma unroll
            for (int np = 0; np < 2; np++)
                ldsm_x4(bq[np], brow + (np * 16 * APAD + ks * 16) * 2);
#pragma unroll
            for (int mt = 0; mt < 4; mt++)
#pragma unroll
                for (int np = 0; np < 2; np++) {
                    uint32_t b0[2] = { bq[np][0], bq[np][2] };
                    uint32_t b1[2] = { bq[np][1], bq[np][3] };
                    mma16816(c[mt][np * 2 + 0], af[mt], b0);
                    mma16816(c[mt][np * 2 + 1], af[mt], b1);
                }
        }
    }

    const int rfrag = lane >> 2;
    const int cfrag = (lane & 3) * 2;
#pragma unroll
    for (int mt = 0; mt < 4; mt++) {
        const int rm0 = bm + warp_m * 64 + mt * 16 + rfrag;
#pragma unroll
        for (int half = 0; half < 2; half++) {
            const int rm = rm0 + half * 8;
            if (rm >= MM) continue;
            int b_ = 0, l_ = 0;
            if (MODE == 1) { b_ = rm / LL; l_ = rm - b_ * LL; }
#pragma unroll
            for (int nt = 0; nt < 4; nt++) {
                const int cn = bn + warp_n * 32 + nt * 8 + cfrag;
                float2 vv = make_float2(c[mt][nt][half * 2 + 0], c[mt][nt][half * 2 + 1]);
                if (MODE == 0) {
                    vv.x += bias[cn];
                    vv.y += bias[cn + 1];
                    *reinterpret_cast<float2*>(&C0[(size_t)rm * DD + cn]) = vv;
                } else {
                    const int mat = cn >> 10;
                    const int cc  = cn & 1023;
                    const int h   = cc >> 7;
                    const int d   = cc & 127;
                    float* base = (mat == 0) ? C0 : (mat == 1) ? C1 : C2;
                    *reinterpret_cast<float2*>(
                        &base[(((size_t)(b_ * HH + h)) * LL + l_) * HD + d]) = vv;
                }
            }
        }
    }
}

// ---------------------------------------------------------------------------
// fp32 -> fp16 conversion (vectorized: float4 in, 4x half packed out)
// ---------------------------------------------------------------------------
__global__ void __launch_bounds__(256)
conv_half(const float* __restrict__ in, __half* __restrict__ out)
{
    const size_t row = blockIdx.x;
    const int c0 = threadIdx.x * 4;
    float4 x = *reinterpret_cast<const float4*>(&in[row * DD + c0]);
    __half2 h0 = __floats2half2_rn(x.x, x.y);
    __half2 h1 = __floats2half2_rn(x.z, x.w);
    uint2 packed = make_uint2(*reinterpret_cast<uint32_t*>(&h0),
                              *reinterpret_cast<uint32_t*>(&h1));
    *reinterpret_cast<uint2*>(&out[row * DD + c0]) = packed;
}

// Weight transpose (batched): W[k][n] fp32 -> Wt[n][k] fp16
__global__ void __launch_bounds__(256)
conv_w3(const float* __restrict__ Wa, const float* __restrict__ Wb,
        const float* __restrict__ Wc,
        __half* __restrict__ Ta, __half* __restrict__ Tb, __half* __restrict__ Tc)
{
    const float* W = (blockIdx.z == 0) ? Wa : (blockIdx.z == 1) ? Wb : Wc;
    __half*      T = (blockIdx.z == 0) ? Ta : (blockIdx.z == 1) ? Tb : Tc;
    __shared__ float tile[32][33];
    const int n0 = blockIdx.x * 32, k0 = blockIdx.y * 32;
    const int tx = threadIdx.x & 31, ty = threadIdx.x >> 5;
#pragma unroll
    for (int i = ty; i < 32; i += 8)
        tile[i][tx] = W[(size_t)(k0 + i) * DD + n0 + tx];
    __syncthreads();
#pragma unroll
    for (int i = ty; i < 32; i += 8)
        T[(size_t)(n0 + i) * DD + k0 + tx] = __float2half(tile[tx][i]);
}

__global__ void __launch_bounds__(256)
conv_w2(const float* __restrict__ Wa, const float* __restrict__ Wb,
        __half* __restrict__ Ta, __half* __restrict__ Tb)
{
    const float* W = (blockIdx.z == 0) ? Wa : Wb;
    __half*      T = (blockIdx.z == 0) ? Ta : Tb;
    __shared__ float tile[32][33];
    const int n0 = blockIdx.x * 32, k0 = blockIdx.y * 32;
    const int tx = threadIdx.x & 31, ty = threadIdx.x >> 5;
#pragma unroll
    for (int i = ty; i < 32; i += 8)
        tile[i][tx] = W[(size_t)(k0 + i) * DD + n0 + tx];
    __syncthreads();
#pragma unroll
    for (int i = ty; i < 32; i += 8)
        T[(size_t)(n0 + i) * DD + k0 + tx] = __float2half(tile[tx][i]);
}

// ---------------------------------------------------------------------------
// LayerNorm over D=1024, fp16 output. Vectorized float4 / packed-half2 I/O.
// GATHER=0: row-major in. GATHER=1: head-merge gather from (nh, L, HD)
//   (4 consecutive elements stay inside one 128-wide head: 4 | 128).
// ---------------------------------------------------------------------------
template<int GATHER>
__global__ void __launch_bounds__(256)
ln_half(const float* __restrict__ in, const float* __restrict__ g,
        const float* __restrict__ beta, __half* __restrict__ out)
{
    const int row = blockIdx.x;
    const int tid = threadIdx.x;
    const int c0 = tid * 4;

    float4 x;
    if (GATHER) {
        const int b_ = row / LL;
        const int l_ = row - b_ * LL;
        const int h = c0 >> 7, d = c0 & 127;
        x = *reinterpret_cast<const float4*>(
            &in[(((size_t)(b_ * HH + h)) * LL + l_) * HD + d]);
    } else {
        x = *reinterpret_cast<const float4*>(&in[(size_t)row * DD + c0]);
    }

    float s  = x.x + x.y + x.z + x.w;
    float ss = x.x * x.x + x.y * x.y + x.z * x.z + x.w * x.w;

    __shared__ float rs[32], rss[32];
#pragma unroll
    for (int o = 16; o > 0; o >>= 1) {
        s  += __shfl_xor_sync(0xffffffffu, s,  o);
        ss += __shfl_xor_sync(0xffffffffu, ss, o);
    }
    int warp = tid >> 5, lane = tid & 31;
    if (lane == 0) { rs[warp] = s; rss[warp] = ss; }
    __syncthreads();
    if (warp == 0) {
        float s2  = (lane < 8) ? rs[lane]  : 0.f;
        float ss2 = (lane < 8) ? rss[lane] : 0.f;
#pragma unroll
        for (int o = 4; o > 0; o >>= 1) {
            s2  += __shfl_xor_sync(0xffffffffu, s2,  o);
            ss2 += __shfl_xor_sync(0xffffffffu, ss2, o);
        }
        if (lane == 0) { rs[0] = s2; rss[0] = ss2; }
    }
    __syncthreads();
    s = rs[0]; ss = rss[0];

    float mean = s * (1.f / 1024.f);
    float var  = ss * (1.f / 1024.f) - mean * mean;
    float rstd = rsqrtf(var + 1e-5f);

    float4 gg = *reinterpret_cast<const float4*>(&g[c0]);
    float4 bb = *reinterpret_cast<const float4*>(&beta[c0]);
    float y0 = (x.x - mean) * rstd * gg.x + bb.x;
    float y1 = (x.y - mean) * rstd * gg.y + bb.y;
    float y2 = (x.z - mean) * rstd * gg.z + bb.z;
    float y3 = (x.w - mean) * rstd * gg.w + bb.w;
    __half2 h0 = __floats2half2_rn(y0, y1);
    __half2 h1 = __floats2half2_rn(y2, y3);
    uint2 packed = make_uint2(*reinterpret_cast<uint32_t*>(&h0),
                              *reinterpret_cast<uint32_t*>(&h1));
    *reinterpret_cast<uint2*>(&out[(size_t)row * DD + c0]) = packed;
}

// ---------------------------------------------------------------------------
// Temporal attention — register-blocked (R12/R13 version; re-bench for DVFS).
// Scores: 136 threads (17 j x 8 d-slices), 16 f-accumulators in regs;
//         ks padded to stride 129 (kills the 17-way j-conflict).
// Output: thread = (d, f-group of 8); vs loaded once per (j,d).
// ---------------------------------------------------------------------------
__global__ void __launch_bounds__(256)
attn_temporal(const float* __restrict__ q, const float* __restrict__ k,
              const float* __restrict__ v, float* __restrict__ out,
              const int* __restrict__ att_type)
{
    if (*att_type != 1) return;
    const int blk = blockIdx.x;
    const int bh  = blk / SS;
    const int s   = blk - bh * SS;
    const int featIdx = blk % NH;        // jnp.tile head-scramble (verified R1)

    __shared__ float qs[FF][HD];
    __shared__ float ks[FF + 1][HD + 1];
    __shared__ float vs[FF + 1][HD];
    __shared__ float spart[8][FF][FF + 1];
    __shared__ float sc[FF][FF + 1];

    const int tid = threadIdx.x;
    const float* qb = q + (size_t)bh * LL * HD;
    const float* kb = k + (size_t)bh * LL * HD;
    const float* vb = v + (size_t)bh * LL * HD;
    const float* kf = k + (size_t)featIdx * LL * HD;
    const float* vf = v + (size_t)featIdx * LL * HD;

    for (int i = tid; i < FF * HD; i += 256) {
        int f = i >> 7, d = i & 127;
        qs[f][d] = qb[(size_t)(1 + f * SS + s) * HD + d];
    }
    for (int i = tid; i < (FF + 1) * HD; i += 256) {
        int j = i >> 7, d = i & 127;
        if (j == 0) { ks[0][d] = kf[d]; vs[0][d] = vf[d]; }
        else {
            size_t l = (size_t)(1 + (j - 1) * SS + s) * HD + d;
            ks[j][d] = kb[l];
            vs[j][d] = vb[l];
        }
    }
    __syncthreads();

    if (tid < 136) {
        const int j     = tid % 17;
        const int slice = tid / 17;          // 0..7, 16 d each
        float acc[FF];
#pragma unroll
        for (int f = 0; f < FF; f++) acc[f] = 0.f;
#pragma unroll
        for (int dd = 0; dd < 16; dd++) {
            const int d = slice * 16 + dd;
            const float kv = ks[j][d];
#pragma unroll
            for (int f = 0; f < FF; f++) acc[f] += qs[f][d] * kv;
        }
#pragma unroll
        for (int f = 0; f < FF; f++) spart[slice][f][j] = acc[f];
    }
    __syncthreads();

    for (int p = tid; p < FF * (FF + 1); p += 256) {
        const int f = p / (FF + 1);
        const int j = p - f * (FF + 1);
        float a = 0.f;
#pragma unroll
        for (int sl = 0; sl < 8; sl++) a += spart[sl][f][j];
        sc[f][j] = a * 0.08838834764831844f;   // 1/sqrt(128)
    }
    __syncthreads();

    if (tid < FF) {
        float mx = sc[tid][0];
#pragma unroll
        for (int j = 1; j <= FF; j++) mx = fmaxf(mx, sc[tid][j]);
        float sum = 0.f;
#pragma unroll
        for (int j = 0; j <= FF; j++) {
            float e = expf(sc[tid][j] - mx);
            sc[tid][j] = e; sum += e;
        }
        float inv = 1.f / sum;
#pragma unroll
        for (int j = 0; j <= FF; j++) sc[tid][j] *= inv;
    }
    __syncthreads();

    {
        const int d = tid & 127;
        const int g = tid >> 7;
        float acc8[8];
#pragma unroll
        for (int f8 = 0; f8 < 8; f8++) acc8[f8] = 0.f;
#pragma unroll
        for (int j = 0; j <= FF; j++) {
            const float vv = vs[j][d];
#pragma unroll
            for (int f8 = 0; f8 < 8; f8++)
                acc8[f8] += sc[g * 8 + f8][j] * vv;
        }
#pragma unroll
        for (int f8 = 0; f8 < 8; f8++) {
            const int f = g * 8 + f8;
            out[(size_t)bh * LL * HD + (size_t)(1 + f * SS + s) * HD + d] = acc8[f8];
        }
    }

    if (s == 0) {
        for (int d = tid; d < HD; d += 256)
            out[(size_t)bh * LL * HD + d] = qb[d];
    }
}

// ---------------------------------------------------------------------------
// Spatial attention fallback (att_type != 1; unused with this dataset)
// ---------------------------------------------------------------------------
__global__ void __launch_bounds__(256)
attn_spatial(const float* __restrict__ q, const float* __restrict__ k,
             const float* __restrict__ v, float* __restrict__ out,
             const int* __restrict__ att_type)
{
    if (*att_type == 1) return;
    const int bh = blockIdx.x / FF;
    const int f  = blockIdx.x - bh * FF;
    const int featIdx = blockIdx.x % NH;

    const float* qb = q + (size_t)bh * LL * HD;
    const float* kb = k + (size_t)bh * LL * HD;
    const float* vb = v + (size_t)bh * LL * HD;
    const float* kf = k + (size_t)featIdx * LL * HD;
    const float* vf = v + (size_t)featIdx * LL * HD;

    __shared__ float qs[HD];
    __shared__ float sc[SS + 1];
    __shared__ float red0;

    const int tid = threadIdx.x;
    for (int s = 0; s < SS; s++) {
        int lq = 1 + f * SS + s;
        for (int d = tid; d < HD; d += 256) qs[d] = qb[(size_t)lq * HD + d];
        __syncthreads();

        for (int j = tid; j <= SS; j += 256) {
            const float* kr = (j == 0) ? kf : &kb[(size_t)(1 + f * SS + (j - 1)) * HD];
            float a = 0.f;
            for (int d = 0; d < HD; d++) a += qs[d] * kr[d];
            sc[j] = a * 0.08838834764831844f;
        }
        __syncthreads();

        if (tid == 0) {
            float mx = sc[0];
            for (int j = 1; j <= SS; j++) mx = fmaxf(mx, sc[j]);
            float sum = 0.f;
            for (int j = 0; j <= SS; j++) { float e = expf(sc[j] - mx); sc[j] = e; sum += e; }
            red0 = 1.f / sum;
        }
        __syncthreads();
        float inv = red0;

        for (int d = tid; d < HD; d += 256) {
            float a = 0.f;
            for (int j = 0; j <= SS; j++) {
                const float* vr = (j == 0) ? vf : &vb[(size_t)(1 + f * SS + (j - 1)) * HD];
                a += sc[j] * vr[d];
            }
            out[(size_t)bh * LL * HD + (size_t)lq * HD + d] = a * inv;
        }
        __syncthreads();
    }
    if (f == 0) {
        for (int d = tid; d < HD; d += 256)
            out[(size_t)bh * LL * HD + d] = qb[d];
    }
}

// ---------------------------------------------------------------------------
// Launch
// ---------------------------------------------------------------------------
extern "C" void kernel_launch(void* const* d_in, const int* in_sizes, int n_in,
                              void* d_out, int out_size)
{
    const float* x       = (const float*)d_in[0];
    const float* W_in    = (const float*)d_in[1];
    const float* b_in    = (const float*)d_in[2];
    const float* g_in    = (const float*)d_in[3];
    const float* beta_in = (const float*)d_in[4];
    const float* W_q     = (const float*)d_in[5];
    const float* W_k     = (const float*)d_in[6];
    const float* W_v     = (const float*)d_in[7];
    const float* g_out_p = (const float*)d_in[8];
    const float* beta_out= (const float*)d_in[9];
    const float* W_out   = (const float*)d_in[10];
    const float* b_out   = (const float*)d_in[11];
    const int*   att_type= (const int*)d_in[12];
    float* out = (float*)d_out;

    __half *p_xh, *p_lnh, *p_win, *p_wout, *p_wqkv;
    float *p_tmp0, *p_q, *p_k, *p_v, *p_attn;
    cudaGetSymbolAddress((void**)&p_xh,   g_xh);
    cudaGetSymbolAddress((void**)&p_lnh,  g_lnh);
    cudaGetSymbolAddress((void**)&p_tmp0, g_tmp0);
    cudaGetSymbolAddress((void**)&p_q,    g_q);
    cudaGetSymbolAddress((void**)&p_k,    g_k);
    cudaGetSymbolAddress((void**)&p_v,    g_v);
    cudaGetSymbolAddress((void**)&p_attn, g_attn);
    cudaGetSymbolAddress((void**)&p_win,  g_win);
    cudaGetSymbolAddress((void**)&p_wout, g_wout);
    cudaGetSymbolAddress((void**)&p_wqkv, g_wqkv);

    cudaFuncSetAttribute(gemm_mma<0>, cudaFuncAttributeMaxDynamicSharedMemorySize, GEMM_SMEM);
    cudaFuncSetAttribute(gemm_mma<1>, cudaFuncAttributeMaxDynamicSharedMemorySize, GEMM_SMEM);

    dim3 wg3(32, 32, 3), wg2(32, 32, 2);
    conv_w3<<<wg3, 256>>>(W_in, W_q, W_k, p_win, p_wqkv, p_wqkv + (size_t)DD * DD);
    conv_w2<<<wg2, 256>>>(W_v, W_out, p_wqkv + (size_t)2 * DD * DD, p_wout);
    conv_half<<<MM, 256>>>(x, p_xh);

    dim3 g1(DD / BN, (MM + BM - 1) / BM);          // (8, 197)
    dim3 g3(3 * DD / BN, (MM + BM - 1) / BM);      // (24, 197)

    gemm_mma<0><<<g1, 256, GEMM_SMEM>>>(p_xh, p_win, b_in, p_tmp0, nullptr, nullptr);
    ln_half<0><<<MM, 256>>>(p_tmp0, g_in, beta_in, p_lnh);
    gemm_mma<1><<<g3, 256, GEMM_SMEM>>>(p_lnh, p_wqkv, nullptr, p_q, p_k, p_v);

    attn_temporal<<<NH * SS, 256>>>(p_q, p_k, p_v, p_attn, att_type);
    attn_spatial <<<NH * FF, 256>>>(p_q, p_k, p_v, p_attn, att_type);

    ln_half<1><<<MM, 256>>>(p_attn, g_out_p, beta_out, p_xh);
    gemm_mma<0><<<g1, 256, GEMM_SMEM>>>(p_xh, p_wout, b_out, out, nullptr, nullptr);
}